// round 3
// baseline (speedup 1.0000x reference)
#include <cuda_runtime.h>
#include <cuda_bf16.h>

#define B_ROWS 16384
#define N_DIM  1000
#define BM 128
#define BN 128
#define BK 8
#define TM 8
#define TN 8

// Scratch for PM = P / M[:,None]  (4 MB, static device allocation -> allowed)
__device__ float g_PM[N_DIM * N_DIM];

__global__ void pm_kernel(const float* __restrict__ P, const float* __restrict__ M) {
    int idx = blockIdx.x * blockDim.x + threadIdx.x;
    if (idx < N_DIM * N_DIM) {
        int n = idx / N_DIM;
        g_PM[idx] = P[idx] / M[n];
    }
}

__global__ void zero_kernel(float* __restrict__ out) {
    int idx = blockIdx.x * blockDim.x + threadIdx.x;
    if (idx < B_ROWS) out[idx] = 0.0f;
}

// losses[b] = (1/N) * sum_{n,k} Y[b,n] * PM[n,k] * Y[b,k]
// Tiled as GEMM C = Y @ PM^T fused with epilogue rowsum(Y .* C).
__global__ __launch_bounds__(256) void qf_kernel(const float* __restrict__ Y,
                                                 float* __restrict__ out) {
    __shared__ float Ys[BK][BM];   // Y tile, transposed:  Ys[k][m]
    __shared__ float Ps[BK][BN];   // PM tile, transposed: Ps[k][n]

    const int tid = threadIdx.x;
    const int tx  = tid & 15;   // n direction (16 threads * TN=8 -> 128)
    const int ty  = tid >> 4;   // m direction (16 threads * TM=8 -> 128)
    const int rowBase = blockIdx.y * BM;
    const int colBase = blockIdx.x * BN;

    float acc[TM][TN];
    #pragma unroll
    for (int i = 0; i < TM; i++)
        #pragma unroll
        for (int j = 0; j < TN; j++) acc[i][j] = 0.0f;

    // cooperative-load indices: 64 rows x 4 float2 per pass, 2 passes
    const int lrow = tid >> 2;         // 0..63
    const int lk   = (tid & 3) * 2;    // 0,2,4,6

    for (int k0 = 0; k0 < N_DIM; k0 += BK) {
        // --- Y tile: rows [rowBase, rowBase+128), cols [k0, k0+8) ---
        #pragma unroll
        for (int h = 0; h < 2; h++) {
            int r = lrow + h * 64;
            const float2 v = *reinterpret_cast<const float2*>(
                &Y[(size_t)(rowBase + r) * N_DIM + k0 + lk]);
            Ys[lk    ][r] = v.x;
            Ys[lk + 1][r] = v.y;
        }
        // --- PM tile: rows (n) [colBase, colBase+128), cols [k0, k0+8) ---
        #pragma unroll
        for (int h = 0; h < 2; h++) {
            int n  = lrow + h * 64;
            int gn = colBase + n;
            float2 v = make_float2(0.0f, 0.0f);
            if (gn < N_DIM)
                v = *reinterpret_cast<const float2*>(
                    &g_PM[(size_t)gn * N_DIM + k0 + lk]);
            Ps[lk    ][n] = v.x;
            Ps[lk + 1][n] = v.y;
        }
        __syncthreads();

        #pragma unroll
        for (int kk = 0; kk < BK; kk++) {
            float a[TM], b[TN];
            #pragma unroll
            for (int i = 0; i < TM; i++) a[i] = Ys[kk][ty * TM + i];
            #pragma unroll
            for (int j = 0; j < TN; j++) b[j] = Ps[kk][tx * TN + j];
            #pragma unroll
            for (int i = 0; i < TM; i++)
                #pragma unroll
                for (int j = 0; j < TN; j++)
                    acc[i][j] += a[i] * b[j];
        }
        __syncthreads();
    }

    // Epilogue: partial[b] = sum_j acc[i][j] * Y[b, col_j]; reduce over tx; atomicAdd.
    const float invN = 1.0f / (float)N_DIM;
    #pragma unroll
    for (int i = 0; i < TM; i++) {
        const int row = rowBase + ty * TM + i;
        float partial = 0.0f;
        #pragma unroll
        for (int j = 0; j < TN; j++) {
            const int col = colBase + tx * TN + j;
            if (col < N_DIM)
                partial += acc[i][j] * Y[(size_t)row * N_DIM + col];
        }
        // reduce across the 16 tx lanes (xor offsets < 16 stay inside each half-warp)
        #pragma unroll
        for (int off = 8; off >= 1; off >>= 1)
            partial += __shfl_xor_sync(0xffffffffu, partial, off);
        if (tx == 0)
            atomicAdd(&out[row], partial * invN);
    }
}

extern "C" void kernel_launch(void* const* d_in, const int* in_sizes, int n_in,
                              void* d_out, int out_size) {
    const float* y_pred = (const float*)d_in[0];
    // d_in[1] = y_true (unused by the loss)
    const float* P = (const float*)d_in[2];
    const float* M = (const float*)d_in[3];
    float* out = (float*)d_out;

    (void)in_sizes; (void)n_in; (void)out_size;

    pm_kernel<<<(N_DIM * N_DIM + 255) / 256, 256>>>(P, M);
    zero_kernel<<<(B_ROWS + 255) / 256, 256>>>(out);

    dim3 grid((N_DIM + BN - 1) / BN, B_ROWS / BM);  // (8, 128)
    qf_kernel<<<grid, 256>>>(y_pred, out);
}

// round 4
// speedup vs baseline: 6.0627x; 6.0627x over previous
#include <cuda_runtime.h>
#include <cuda_bf16.h>
#include <cstdint>

#define B_ROWS 16384
#define N_DIM  1000
#define N_PAD  1024
#define BM 128
#define BN 128
#define BK 32
#define NITER (N_PAD / BK)   // 32

// Static device scratch (no allocation): PMb 2MB, Yb 33.5MB
__device__ __nv_bfloat16 g_PMb[N_PAD * N_PAD];
__device__ __nv_bfloat16 g_Yb[(size_t)B_ROWS * N_PAD];

// ---------------- pre-kernels ----------------
__global__ void pm_kernel(const float* __restrict__ P, const float* __restrict__ M) {
    int idx = blockIdx.x * blockDim.x + threadIdx.x;  // over 1024*1024
    int n = idx >> 10, k = idx & 1023;
    float v = 0.0f;
    if (n < N_DIM && k < N_DIM) v = P[n * N_DIM + k] / M[n];
    g_PMb[idx] = __float2bfloat16_rn(v);
}

struct alignas(16) bf8 { __nv_bfloat16 v[8]; };

__global__ void yb_kernel(const float* __restrict__ Y) {
    int idx = blockIdx.x * blockDim.x + threadIdx.x;  // over 16384*128
    int b = idx >> 7, chunk = idx & 127;
    bf8 o;
    if (chunk < 125) {  // 1000/8 = 125 exact
        const float4 f0 = *reinterpret_cast<const float4*>(&Y[(size_t)b * N_DIM + chunk * 8]);
        const float4 f1 = *reinterpret_cast<const float4*>(&Y[(size_t)b * N_DIM + chunk * 8 + 4]);
        o.v[0] = __float2bfloat16_rn(f0.x); o.v[1] = __float2bfloat16_rn(f0.y);
        o.v[2] = __float2bfloat16_rn(f0.z); o.v[3] = __float2bfloat16_rn(f0.w);
        o.v[4] = __float2bfloat16_rn(f1.x); o.v[5] = __float2bfloat16_rn(f1.y);
        o.v[6] = __float2bfloat16_rn(f1.z); o.v[7] = __float2bfloat16_rn(f1.w);
    } else {
        #pragma unroll
        for (int i = 0; i < 8; i++) o.v[i] = __float2bfloat16_rn(0.0f);
    }
    *reinterpret_cast<bf8*>(&g_Yb[(size_t)b * N_PAD + chunk * 8]) = o;
}

__global__ void zero_kernel(float* __restrict__ out) {
    int idx = blockIdx.x * blockDim.x + threadIdx.x;
    if (idx < B_ROWS) out[idx] = 0.0f;
}

// ---------------- tensor-core helpers ----------------
__device__ __forceinline__ void ldsm_x4(uint32_t& r0, uint32_t& r1, uint32_t& r2, uint32_t& r3,
                                        const void* sptr) {
    uint32_t addr = (uint32_t)__cvta_generic_to_shared(sptr);
    asm volatile("ldmatrix.sync.aligned.m8n8.x4.shared.b16 {%0,%1,%2,%3}, [%4];"
                 : "=r"(r0), "=r"(r1), "=r"(r2), "=r"(r3) : "r"(addr));
}

__device__ __forceinline__ void mma_bf16(float* c, const uint32_t* a, const uint32_t* b) {
    asm volatile(
        "mma.sync.aligned.m16n8k16.row.col.f32.bf16.bf16.f32 "
        "{%0,%1,%2,%3}, {%4,%5,%6,%7}, {%8,%9}, {%0,%1,%2,%3};"
        : "+f"(c[0]), "+f"(c[1]), "+f"(c[2]), "+f"(c[3])
        : "r"(a[0]), "r"(a[1]), "r"(a[2]), "r"(a[3]), "r"(b[0]), "r"(b[1]));
}

__device__ __forceinline__ void cp_async16(void* sptr, const void* gptr) {
    uint32_t addr = (uint32_t)__cvta_generic_to_shared(sptr);
    asm volatile("cp.async.cg.shared.global [%0], [%1], 16;" :: "r"(addr), "l"(gptr));
}
__device__ __forceinline__ void cp_commit() { asm volatile("cp.async.commit_group;"); }
template <int N> __device__ __forceinline__ void cp_wait() {
    asm volatile("cp.async.wait_group %0;" :: "n"(N));
}

// ---------------- main fused QF kernel ----------------
// losses[b] = (1/1000) * sum_{n,k} Yb[b,n] * PMb[n,k] * Yb[b,k]
// C = Yb @ PMb^T (bf16 mma, fp32 accum), epilogue rowsum(Yb .* C) from fragments.
#define SM_STRIDE 40   // 32 + 8 pad: 80B rows, conflict-free ldmatrix phases

__global__ __launch_bounds__(256) void qf_tc_kernel(float* __restrict__ out) {
    __shared__ __nv_bfloat16 As[2][BM][SM_STRIDE];
    __shared__ __nv_bfloat16 Bs[2][BN][SM_STRIDE];

    const int tid  = threadIdx.x;
    const int lane = tid & 31;
    const int w    = tid >> 5;          // 0..7
    const int wm   = w >> 2;            // 0..1  (64 rows each)
    const int wn   = w & 3;             // 0..3  (32 cols each)
    const int g    = lane >> 2;         // group 0..7
    const int tig  = lane & 3;

    const int rowBase = blockIdx.y * BM;
    const int colBase = blockIdx.x * BN;

    // ldmatrix lane mappings
    const int arow = lane & 15, acol = (lane >> 4) * 8;          // A x4
    const int bt = lane >> 3, brow = lane & 7;                   // B x4
    const int bn_off = (bt >> 1) * 8 + brow, bk_off = (bt & 1) * 8;

    // cp.async mapping: thread -> (row, two 16B chunks)
    const int ldrow = tid >> 1;
    const int ldc0  = (tid & 1) * 2;    // chunks {0,1} or {2,3}

    float acc[4][4][4];
    #pragma unroll
    for (int mi = 0; mi < 4; mi++)
        #pragma unroll
        for (int ni = 0; ni < 4; ni++)
            #pragma unroll
            for (int r = 0; r < 4; r++) acc[mi][ni][r] = 0.0f;

    const __nv_bfloat16* Ag = &g_Yb[(size_t)(rowBase + ldrow) * N_PAD];
    const __nv_bfloat16* Bg = &g_PMb[(size_t)(colBase + ldrow) * N_PAD];

    // prologue: load tile 0 into buf 0
    #pragma unroll
    for (int c = 0; c < 2; c++) {
        cp_async16(&As[0][ldrow][(ldc0 + c) * 8], Ag + (ldc0 + c) * 8);
        cp_async16(&Bs[0][ldrow][(ldc0 + c) * 8], Bg + (ldc0 + c) * 8);
    }
    cp_commit();

    for (int it = 0; it < NITER; it++) {
        const int cur = it & 1;
        if (it + 1 < NITER) {
            const int nxt = cur ^ 1, k0 = (it + 1) * BK;
            #pragma unroll
            for (int c = 0; c < 2; c++) {
                cp_async16(&As[nxt][ldrow][(ldc0 + c) * 8], Ag + k0 + (ldc0 + c) * 8);
                cp_async16(&Bs[nxt][ldrow][(ldc0 + c) * 8], Bg + k0 + (ldc0 + c) * 8);
            }
            cp_commit();
            cp_wait<1>();
        } else {
            cp_wait<0>();
        }
        __syncthreads();

        #pragma unroll
        for (int ks = 0; ks < 2; ks++) {
            uint32_t a[4][4], b[4][2];
            #pragma unroll
            for (int mi = 0; mi < 4; mi++)
                ldsm_x4(a[mi][0], a[mi][1], a[mi][2], a[mi][3],
                        &As[cur][wm * 64 + mi * 16 + arow][ks * 16 + acol]);
            #pragma unroll
            for (int j = 0; j < 2; j++)
                ldsm_x4(b[2 * j][0], b[2 * j][1], b[2 * j + 1][0], b[2 * j + 1][1],
                        &Bs[cur][wn * 32 + j * 16 + bn_off][ks * 16 + bk_off]);
            #pragma unroll
            for (int mi = 0; mi < 4; mi++)
                #pragma unroll
                for (int ni = 0; ni < 4; ni++)
                    mma_bf16(acc[mi][ni], a[mi], b[ni]);
        }
        __syncthreads();   // protect buf `cur` before it is refilled at it+2
    }

    // Epilogue: partial[b] += sum_col acc * Yb[b, col]; reduce over tig; atomicAdd
    const float invN = 1.0f / (float)N_DIM;
    #pragma unroll
    for (int mi = 0; mi < 4; mi++) {
        const int row0 = rowBase + wm * 64 + mi * 16 + g;   // and row0+8
        float p0 = 0.0f, p1 = 0.0f;
        #pragma unroll
        for (int ni = 0; ni < 4; ni++) {
            const int col = colBase + wn * 32 + ni * 8 + tig * 2;
            const uint32_t y0 = *reinterpret_cast<const uint32_t*>(
                &g_Yb[(size_t)row0 * N_PAD + col]);
            const uint32_t y1 = *reinterpret_cast<const uint32_t*>(
                &g_Yb[(size_t)(row0 + 8) * N_PAD + col]);
            const float y0a = __uint_as_float(y0 << 16);
            const float y0b = __uint_as_float(y0 & 0xffff0000u);
            const float y1a = __uint_as_float(y1 << 16);
            const float y1b = __uint_as_float(y1 & 0xffff0000u);
            p0 += acc[mi][ni][0] * y0a + acc[mi][ni][1] * y0b;
            p1 += acc[mi][ni][2] * y1a + acc[mi][ni][3] * y1b;
        }
        // reduce across the 4 tig lanes (same group)
        #pragma unroll
        for (int off = 1; off <= 2; off <<= 1) {
            p0 += __shfl_xor_sync(0xffffffffu, p0, off);
            p1 += __shfl_xor_sync(0xffffffffu, p1, off);
        }
        if (tig == 0) {
            atomicAdd(&out[row0], p0 * invN);
            atomicAdd(&out[row0 + 8], p1 * invN);
        }
    }
}

extern "C" void kernel_launch(void* const* d_in, const int* in_sizes, int n_in,
                              void* d_out, int out_size) {
    const float* y_pred = (const float*)d_in[0];
    // d_in[1] = y_true (unused)
    const float* P = (const float*)d_in[2];
    const float* M = (const float*)d_in[3];
    float* out = (float*)d_out;
    (void)in_sizes; (void)n_in; (void)out_size;

    pm_kernel<<<(N_PAD * N_PAD) / 256, 256>>>(P, M);
    yb_kernel<<<(B_ROWS * (N_PAD / 8)) / 256, 256>>>(y_pred);
    zero_kernel<<<B_ROWS / 256, 256>>>(out);

    dim3 grid(N_PAD / BN, B_ROWS / BM);   // (8, 128)
    qf_tc_kernel<<<grid, 256>>>(out);
}

// round 6
// speedup vs baseline: 6.9766x; 1.1507x over previous
#include <cuda_runtime.h>
#include <cuda_bf16.h>
#include <cstdint>

#define B_ROWS 16384
#define N_DIM  1000
#define N_PAD  1024
#define BM 128
#define BN 128
#define BK 32
#define NITER (N_PAD / BK)   // 32
#define NSTAGE 4
#define SM_STRIDE 40         // 32 + 8 pad: 80B rows, conflict-free ldmatrix phases

// Static device scratch (no allocation): PMb 2MB, Yb 33.5MB
__device__ __nv_bfloat16 g_PMb[N_PAD * N_PAD];
__device__ __nv_bfloat16 g_Yb[(size_t)B_ROWS * N_PAD];

// ---------------- pre-kernels (known good) ----------------
__global__ void pm_kernel(const float* __restrict__ P, const float* __restrict__ M) {
    int idx = blockIdx.x * blockDim.x + threadIdx.x;  // over 1024*1024
    int n = idx >> 10, k = idx & 1023;
    float v = 0.0f;
    if (n < N_DIM && k < N_DIM) v = P[n * N_DIM + k] / M[n];
    g_PMb[idx] = __float2bfloat16_rn(v);
}

struct alignas(16) bf8 { __nv_bfloat16 v[8]; };

__global__ void yb_kernel(const float* __restrict__ Y) {
    int idx = blockIdx.x * blockDim.x + threadIdx.x;  // over 16384*128
    int b = idx >> 7, chunk = idx & 127;
    bf8 o;
    if (chunk < 125) {
        const float4 f0 = *reinterpret_cast<const float4*>(&Y[(size_t)b * N_DIM + chunk * 8]);
        const float4 f1 = *reinterpret_cast<const float4*>(&Y[(size_t)b * N_DIM + chunk * 8 + 4]);
        o.v[0] = __float2bfloat16_rn(f0.x); o.v[1] = __float2bfloat16_rn(f0.y);
        o.v[2] = __float2bfloat16_rn(f0.z); o.v[3] = __float2bfloat16_rn(f0.w);
        o.v[4] = __float2bfloat16_rn(f1.x); o.v[5] = __float2bfloat16_rn(f1.y);
        o.v[6] = __float2bfloat16_rn(f1.z); o.v[7] = __float2bfloat16_rn(f1.w);
    } else {
        #pragma unroll
        for (int i = 0; i < 8; i++) o.v[i] = __float2bfloat16_rn(0.0f);
    }
    *reinterpret_cast<bf8*>(&g_Yb[(size_t)b * N_PAD + chunk * 8]) = o;
}

__global__ void zero_kernel(float* __restrict__ out) {
    int idx = blockIdx.x * blockDim.x + threadIdx.x;
    if (idx < B_ROWS) out[idx] = 0.0f;
}

// ---------------- tensor-core helpers ----------------
__device__ __forceinline__ void ldsm_x4(uint32_t& r0, uint32_t& r1, uint32_t& r2, uint32_t& r3,
                                        const void* sptr) {
    uint32_t addr = (uint32_t)__cvta_generic_to_shared(sptr);
    asm volatile("ldmatrix.sync.aligned.m8n8.x4.shared.b16 {%0,%1,%2,%3}, [%4];"
                 : "=r"(r0), "=r"(r1), "=r"(r2), "=r"(r3) : "r"(addr));
}

__device__ __forceinline__ void mma_bf16(float* c, const uint32_t* a, const uint32_t* b) {
    asm volatile(
        "mma.sync.aligned.m16n8k16.row.col.f32.bf16.bf16.f32 "
        "{%0,%1,%2,%3}, {%4,%5,%6,%7}, {%8,%9}, {%0,%1,%2,%3};"
        : "+f"(c[0]), "+f"(c[1]), "+f"(c[2]), "+f"(c[3])
        : "r"(a[0]), "r"(a[1]), "r"(a[2]), "r"(a[3]), "r"(b[0]), "r"(b[1]));
}

__device__ __forceinline__ void cp_async16(void* sptr, const void* gptr) {
    uint32_t addr = (uint32_t)__cvta_generic_to_shared(sptr);
    asm volatile("cp.async.cg.shared.global [%0], [%1], 16;" :: "r"(addr), "l"(gptr));
}
__device__ __forceinline__ void cp_commit() { asm volatile("cp.async.commit_group;"); }
template <int N> __device__ __forceinline__ void cp_wait() {
    asm volatile("cp.async.wait_group %0;" :: "n"(N));
}

// ---------------- main fused QF kernel ----------------
// losses[b] = (1/1000) * sum_{n,k} Yb[b,n] * PMb[n,k] * Yb[b,k]
// C = Yb @ PMb^T (bf16 mma, fp32 accum), epilogue rowsum(Yb .* C) from fragments.
// 4-stage cp.async pipeline, ONE __syncthreads per K-iteration.
__global__ __launch_bounds__(256, 2) void qf_tc_kernel(float* __restrict__ out) {
    extern __shared__ __nv_bfloat16 dsm[];
    typedef __nv_bfloat16 (*TileA)[BM][SM_STRIDE];
    typedef __nv_bfloat16 (*TileB)[BN][SM_STRIDE];
    TileA As = reinterpret_cast<TileA>(dsm);                                  // [NSTAGE][BM][40]
    TileB Bs = reinterpret_cast<TileB>(dsm + NSTAGE * BM * SM_STRIDE);        // [NSTAGE][BN][40]

    const int tid  = threadIdx.x;
    const int lane = tid & 31;
    const int w    = tid >> 5;          // 0..7
    const int wm   = w >> 2;            // 0..1  (64 rows each)
    const int wn   = w & 3;             // 0..3  (32 cols each)
    const int g    = lane >> 2;         // group 0..7
    const int tig  = lane & 3;

    const int rowBase = blockIdx.y * BM;
    const int colBase = blockIdx.x * BN;

    // ldmatrix lane mappings (proven in round 4)
    const int arow = lane & 15, acol = (lane >> 4) * 8;          // A x4
    const int bt = lane >> 3, brow = lane & 7;                   // B x4
    const int bn_off = (bt >> 1) * 8 + brow, bk_off = (bt & 1) * 8;

    // cp.async mapping: thread -> (row, two 16B chunks)
    const int ldrow = tid >> 1;
    const int ldc0  = (tid & 1) * 2;    // chunks {0,1} or {2,3}

    float acc[4][4][4];
    #pragma unroll
    for (int mi = 0; mi < 4; mi++)
        #pragma unroll
        for (int ni = 0; ni < 4; ni++)
            #pragma unroll
            for (int r = 0; r < 4; r++) acc[mi][ni][r] = 0.0f;

    const __nv_bfloat16* Ag = &g_Yb[(size_t)(rowBase + ldrow) * N_PAD];
    const __nv_bfloat16* Bg = &g_PMb[(size_t)(colBase + ldrow) * N_PAD];

    // prologue: stages 0,1,2 (one commit group each)
    #pragma unroll
    for (int s = 0; s < NSTAGE - 1; s++) {
        const int k0 = s * BK;
        #pragma unroll
        for (int c = 0; c < 2; c++) {
            cp_async16(&As[s][ldrow][(ldc0 + c) * 8], Ag + k0 + (ldc0 + c) * 8);
            cp_async16(&Bs[s][ldrow][(ldc0 + c) * 8], Bg + k0 + (ldc0 + c) * 8);
        }
        cp_commit();
    }

    for (int it = 0; it < NITER; it++) {
        const int cur = it & (NSTAGE - 1);
        // groups committed so far: 0..it+2; leave last 2 in flight -> stage `cur` ready
        cp_wait<2>();
        __syncthreads();   // also guarantees compute of it-1 finished on all warps
                           // -> safe to refill buffer (it+3)&3 == (it-1)&3 below

        // issue loads for stage it+3 (empty commit keeps group accounting uniform)
        if (it + NSTAGE - 1 < NITER) {
            const int nxt = (it + NSTAGE - 1) & (NSTAGE - 1);
            const int k0 = (it + NSTAGE - 1) * BK;
            #pragma unroll
            for (int c = 0; c < 2; c++) {
                cp_async16(&As[nxt][ldrow][(ldc0 + c) * 8], Ag + k0 + (ldc0 + c) * 8);
                cp_async16(&Bs[nxt][ldrow][(ldc0 + c) * 8], Bg + k0 + (ldc0 + c) * 8);
            }
        }
        cp_commit();

        #pragma unroll
        for (int ks = 0; ks < 2; ks++) {
            uint32_t a[4][4], b[4][2];
            #pragma unroll
            for (int mi = 0; mi < 4; mi++)
                ldsm_x4(a[mi][0], a[mi][1], a[mi][2], a[mi][3],
                        &As[cur][wm * 64 + mi * 16 + arow][ks * 16 + acol]);
            #pragma unroll
            for (int j = 0; j < 2; j++)
                ldsm_x4(b[2 * j][0], b[2 * j][1], b[2 * j + 1][0], b[2 * j + 1][1],
                        &Bs[cur][wn * 32 + j * 16 + bn_off][ks * 16 + bk_off]);
            #pragma unroll
            for (int mi = 0; mi < 4; mi++)
                #pragma unroll
                for (int ni = 0; ni < 4; ni++)
                    mma_bf16(acc[mi][ni], a[mi], b[ni]);
        }
    }

    // Epilogue: partial[b] += sum_col acc * Yb[b, col]; reduce over tig; atomicAdd
    const float invN = 1.0f / (float)N_DIM;
    #pragma unroll
    for (int mi = 0; mi < 4; mi++) {
        const int row0 = rowBase + wm * 64 + mi * 16 + g;   // and row0+8
        float p0 = 0.0f, p1 = 0.0f;
        #pragma unroll
        for (int ni = 0; ni < 4; ni++) {
            const int col = colBase + wn * 32 + ni * 8 + tig * 2;
            const uint32_t y0 = *reinterpret_cast<const uint32_t*>(
                &g_Yb[(size_t)row0 * N_PAD + col]);
            const uint32_t y1 = *reinterpret_cast<const uint32_t*>(
                &g_Yb[(size_t)(row0 + 8) * N_PAD + col]);
            const float y0a = __uint_as_float(y0 << 16);
            const float y0b = __uint_as_float(y0 & 0xffff0000u);
            const float y1a = __uint_as_float(y1 << 16);
            const float y1b = __uint_as_float(y1 & 0xffff0000u);
            p0 += acc[mi][ni][0] * y0a + acc[mi][ni][1] * y0b;
            p1 += acc[mi][ni][2] * y1a + acc[mi][ni][3] * y1b;
        }
        #pragma unroll
        for (int off = 1; off <= 2; off <<= 1) {
            p0 += __shfl_xor_sync(0xffffffffu, p0, off);
            p1 += __shfl_xor_sync(0xffffffffu, p1, off);
        }
        if (tig == 0) {
            atomicAdd(&out[row0], p0 * invN);
            atomicAdd(&out[row0 + 8], p1 * invN);
        }
    }
}

#define QF_SMEM_BYTES (NSTAGE * (BM + BN) * SM_STRIDE * (int)sizeof(__nv_bfloat16))  // 81920

extern "C" void kernel_launch(void* const* d_in, const int* in_sizes, int n_in,
                              void* d_out, int out_size) {
    const float* y_pred = (const float*)d_in[0];
    // d_in[1] = y_true (unused)
    const float* P = (const float*)d_in[2];
    const float* M = (const float*)d_in[3];
    float* out = (float*)d_out;
    (void)in_sizes; (void)n_in; (void)out_size;

    cudaFuncSetAttribute(qf_tc_kernel,
                         cudaFuncAttributeMaxDynamicSharedMemorySize, QF_SMEM_BYTES);

    pm_kernel<<<(N_PAD * N_PAD) / 256, 256>>>(P, M);
    yb_kernel<<<(B_ROWS * (N_PAD / 8)) / 256, 256>>>(y_pred);
    zero_kernel<<<B_ROWS / 256, 256>>>(out);

    dim3 grid(N_PAD / BN, B_ROWS / BM);   // (8, 128)
    qf_tc_kernel<<<grid, 256, QF_SMEM_BYTES>>>(out);
}